// round 3
// baseline (speedup 1.0000x reference)
#include <cuda_runtime.h>
#include <cstdint>

#define N_ROWS 16384
#define FEATS  512
#define HID    256
#define CLS    64
#define NITER  10

// ---------------- scratch (no allocations allowed) ----------------
__device__ float g_W[FEATS * CLS];       // W1 @ W2
__device__ float g_bias[CLS];            // b1 @ W2 + b2
__device__ float g_Z0[N_ROWS * CLS];     // MLP output
__device__ float g_ZA[N_ROWS * CLS];     // ping
__device__ float g_ZB[N_ROWS * CLS];     // pong

// ---------------- kernel 1: collapse the MLP (fp32) ----------------
__global__ void fuse_w_kernel(const float* __restrict__ W1,
                              const float* __restrict__ b1,
                              const float* __restrict__ W2,
                              const float* __restrict__ b2) {
    int idx = blockIdx.x * blockDim.x + threadIdx.x;
    if (idx < FEATS * CLS) {
        int f = idx / CLS, c = idx % CLS;
        float s = 0.f;
        #pragma unroll 8
        for (int k = 0; k < HID; k++) s += W1[f * HID + k] * W2[k * CLS + c];
        g_W[idx] = s;
    } else if (idx < FEATS * CLS + CLS) {
        int c = idx - FEATS * CLS;
        float s = b2[c];
        for (int k = 0; k < HID; k++) s += b1[k] * W2[k * CLS + c];
        g_bias[c] = s;
    }
}

// ---------------- kernel 2: Z0 = h @ W + bias (fp32) ----------------
#define Z0_BM 64
#define Z0_BK 16
__global__ __launch_bounds__(256)
void z0_kernel(const float* __restrict__ h) {
    __shared__ float As[Z0_BM][Z0_BK + 1];
    __shared__ float Bs[Z0_BK][CLS + 1];
    int bm = blockIdx.x * Z0_BM;
    int tx = threadIdx.x % 16, ty = threadIdx.x / 16;
    float acc[4][4];
    #pragma unroll
    for (int i = 0; i < 4; i++)
        #pragma unroll
        for (int j = 0; j < 4; j++) acc[i][j] = 0.f;

    for (int k0 = 0; k0 < FEATS; k0 += Z0_BK) {
        for (int i = threadIdx.x; i < Z0_BM * Z0_BK; i += 256) {
            int r = i / Z0_BK, c = i % Z0_BK;
            As[r][c] = h[(size_t)(bm + r) * FEATS + k0 + c];
        }
        for (int i = threadIdx.x; i < Z0_BK * CLS; i += 256) {
            int r = i / CLS, c = i % CLS;
            Bs[r][c] = g_W[(k0 + r) * CLS + c];
        }
        __syncthreads();
        #pragma unroll
        for (int kk = 0; kk < Z0_BK; kk++) {
            float a[4], b[4];
            #pragma unroll
            for (int i = 0; i < 4; i++) a[i] = As[ty * 4 + i][kk];
            #pragma unroll
            for (int j = 0; j < 4; j++) b[j] = Bs[kk][tx * 4 + j];
            #pragma unroll
            for (int i = 0; i < 4; i++)
                #pragma unroll
                for (int j = 0; j < 4; j++) acc[i][j] += a[i] * b[j];
        }
        __syncthreads();
    }
    #pragma unroll
    for (int i = 0; i < 4; i++)
        #pragma unroll
        for (int j = 0; j < 4; j++)
            g_Z0[(size_t)(bm + ty * 4 + i) * CLS + tx * 4 + j] =
                acc[i][j] + g_bias[tx * 4 + j];
}

// ---------------- kernel 3: propagation, pure fp32 SIMT ----------------
// BM=128, BN=64 (all classes), BK=16. 256 threads, thread tile 8(m) x 4(n).
// Double-buffered smem with register prefetch. Reads adj fp32 directly.
#define BM 128
#define BN 64
#define BK 16
#define KT (N_ROWS / BK)   // 1024

__global__ __launch_bounds__(256, 1)
void prop_kernel(const float* __restrict__ adj, int it) {
    const float* Zin  = (it == 0) ? g_Z0 : ((it & 1) ? g_ZA : g_ZB);
    float*       Zout = (it & 1) ? g_ZB : g_ZA;

    __shared__ float As[2][BK][BM + 4];   // transposed: [k][m]
    __shared__ float Bs[2][BK][BN + 4];   // [k][n]

    const int tid = threadIdx.x;
    const int tx  = tid & 15;     // n0 = tx*4
    const int ty  = tid >> 4;     // m0 = ty*8
    const int bm  = blockIdx.x * BM;

    // A: 128 rows x 16 k = 512 float4; thread handles float4-indices tid, tid+256
    const int ar0 = tid >> 2,        akq0 = tid & 3;
    const int ar1 = (tid + 256) >> 2, akq1 = (tid + 256) & 3;
    // B: 16 rows x 64 = 256 float4; thread handles index tid (tid<256)
    const int br = tid >> 4, bcq = tid & 15;

    float4 pa0, pa1, pb;

    auto ldg = [&](int k0) {
        pa0 = *(const float4*)(adj + (size_t)(bm + ar0) * N_ROWS + k0 + akq0 * 4);
        pa1 = *(const float4*)(adj + (size_t)(bm + ar1) * N_ROWS + k0 + akq1 * 4);
        pb  = *(const float4*)(Zin + (size_t)(k0 + br) * CLS + bcq * 4);
    };
    auto sts = [&](int s) {
        As[s][akq0 * 4 + 0][ar0] = pa0.x;
        As[s][akq0 * 4 + 1][ar0] = pa0.y;
        As[s][akq0 * 4 + 2][ar0] = pa0.z;
        As[s][akq0 * 4 + 3][ar0] = pa0.w;
        As[s][akq1 * 4 + 0][ar1] = pa1.x;
        As[s][akq1 * 4 + 1][ar1] = pa1.y;
        As[s][akq1 * 4 + 2][ar1] = pa1.z;
        As[s][akq1 * 4 + 3][ar1] = pa1.w;
        *(float4*)&Bs[s][br][bcq * 4] = pb;
    };

    float acc[8][4];
    #pragma unroll
    for (int i = 0; i < 8; i++)
        #pragma unroll
        for (int j = 0; j < 4; j++) acc[i][j] = 0.f;

    ldg(0);
    sts(0);
    __syncthreads();

    for (int kt = 0; kt < KT; kt++) {
        if (kt + 1 < KT) ldg((kt + 1) * BK);   // prefetch into registers
        const int s = kt & 1;

        #pragma unroll
        for (int k = 0; k < BK; k++) {
            float a[8], b[4];
            *(float4*)(a)     = *(const float4*)&As[s][k][ty * 8];
            *(float4*)(a + 4) = *(const float4*)&As[s][k][ty * 8 + 4];
            *(float4*)(b)     = *(const float4*)&Bs[s][k][tx * 4];
            #pragma unroll
            for (int i = 0; i < 8; i++)
                #pragma unroll
                for (int j = 0; j < 4; j++) acc[i][j] = fmaf(a[i], b[j], acc[i][j]);
        }
        __syncthreads();
        if (kt + 1 < KT) {
            sts((kt + 1) & 1);
            __syncthreads();
        }
    }

    // epilogue: Zout = 0.9*acc + 0.1*Z0
    #pragma unroll
    for (int i = 0; i < 8; i++) {
        int r = bm + ty * 8 + i;
        #pragma unroll
        for (int j = 0; j < 4; j++) {
            size_t idx = (size_t)r * CLS + tx * 4 + j;
            Zout[idx] = 0.9f * acc[i][j] + 0.1f * g_Z0[idx];
        }
    }
}

// ---------------- kernel 4: row-wise log_softmax (warp per row) ----------------
__global__ __launch_bounds__(256)
void lsm_kernel(float* __restrict__ out) {
    int row  = blockIdx.x * 8 + (threadIdx.x >> 5);
    int lane = threadIdx.x & 31;
    const float* zr = g_ZB + (size_t)row * CLS;   // iteration 9 (odd) -> g_ZB
    float v0 = zr[lane], v1 = zr[lane + 32];
    float m = fmaxf(v0, v1);
    #pragma unroll
    for (int o = 16; o > 0; o >>= 1) m = fmaxf(m, __shfl_xor_sync(0xffffffffu, m, o));
    float e = expf(v0 - m) + expf(v1 - m);
    #pragma unroll
    for (int o = 16; o > 0; o >>= 1) e += __shfl_xor_sync(0xffffffffu, e, o);
    float l = m + logf(e);
    out[(size_t)row * CLS + lane]      = v0 - l;
    out[(size_t)row * CLS + lane + 32] = v1 - l;
}

// ---------------- launch ----------------
extern "C" void kernel_launch(void* const* d_in, const int* in_sizes, int n_in,
                              void* d_out, int out_size) {
    const float *h = nullptr, *adj = nullptr, *W1 = nullptr,
                *b1 = nullptr, *W2 = nullptr, *b2 = nullptr;
    for (int i = 0; i < n_in; i++) {
        switch (in_sizes[i]) {
            case N_ROWS * FEATS:  h   = (const float*)d_in[i]; break;
            case 268435456:       adj = (const float*)d_in[i]; break;
            case FEATS * HID:     W1  = (const float*)d_in[i]; break;
            case HID:             b1  = (const float*)d_in[i]; break;
            case HID * CLS:       W2  = (const float*)d_in[i]; break;
            case CLS:             b2  = (const float*)d_in[i]; break;
            default: break;
        }
    }

    fuse_w_kernel<<<(FEATS * CLS + CLS + 255) / 256, 256>>>(W1, b1, W2, b2);
    z0_kernel<<<N_ROWS / Z0_BM, 256>>>(h);
    for (int it = 0; it < NITER; it++)
        prop_kernel<<<N_ROWS / BM, 256>>>(adj, it);
    lsm_kernel<<<N_ROWS / 8, 256>>>((float*)d_out);
}

// round 6
// speedup vs baseline: 3.6531x; 3.6531x over previous
#include <cuda_runtime.h>
#include <cstdint>

#define N_ROWS 16384
#define FEATS  512
#define HID    256
#define CLS    64
#define NITER  10

// ---------------- scratch (no allocations allowed) ----------------
__device__ float g_W[FEATS * CLS];       // W1 @ W2
__device__ float g_bias[CLS];            // b1 @ W2 + b2
__device__ float g_Z0[N_ROWS * CLS];     // MLP output
__device__ float g_ZA[N_ROWS * CLS];     // ping
__device__ float g_ZB[N_ROWS * CLS];     // pong

// ---------------- kernel 1: collapse the MLP ----------------
__global__ void fuse_w_kernel(const float* __restrict__ W1,
                              const float* __restrict__ b1,
                              const float* __restrict__ W2,
                              const float* __restrict__ b2) {
    int idx = blockIdx.x * blockDim.x + threadIdx.x;
    if (idx < FEATS * CLS) {
        int f = idx / CLS, c = idx % CLS;
        float s = 0.f;
        #pragma unroll 8
        for (int k = 0; k < HID; k++) s += W1[f * HID + k] * W2[k * CLS + c];
        g_W[idx] = s;
    } else if (idx < FEATS * CLS + CLS) {
        int c = idx - FEATS * CLS;
        float s = b2[c];
        for (int k = 0; k < HID; k++) s += b1[k] * W2[k * CLS + c];
        g_bias[c] = s;
    }
}

// ---------------- kernel 2: Z0 = h @ W + bias (fp32, proven) ----------------
#define Z0_BM 64
#define Z0_BK 16
__global__ __launch_bounds__(256)
void z0_kernel(const float* __restrict__ h) {
    __shared__ float As[Z0_BM][Z0_BK + 1];
    __shared__ float Bs[Z0_BK][CLS + 1];
    int bm = blockIdx.x * Z0_BM;
    int tx = threadIdx.x % 16, ty = threadIdx.x / 16;
    float acc[4][4];
    #pragma unroll
    for (int i = 0; i < 4; i++)
        #pragma unroll
        for (int j = 0; j < 4; j++) acc[i][j] = 0.f;

    for (int k0 = 0; k0 < FEATS; k0 += Z0_BK) {
        for (int i = threadIdx.x; i < Z0_BM * Z0_BK; i += 256) {
            int r = i / Z0_BK, c = i % Z0_BK;
            As[r][c] = h[(size_t)(bm + r) * FEATS + k0 + c];
        }
        for (int i = threadIdx.x; i < Z0_BK * CLS; i += 256) {
            int r = i / CLS, c = i % CLS;
            Bs[r][c] = g_W[(k0 + r) * CLS + c];
        }
        __syncthreads();
        #pragma unroll
        for (int kk = 0; kk < Z0_BK; kk++) {
            float a[4], b[4];
            #pragma unroll
            for (int i = 0; i < 4; i++) a[i] = As[ty * 4 + i][kk];
            #pragma unroll
            for (int j = 0; j < 4; j++) b[j] = Bs[kk][tx * 4 + j];
            #pragma unroll
            for (int i = 0; i < 4; i++)
                #pragma unroll
                for (int j = 0; j < 4; j++) acc[i][j] += a[i] * b[j];
        }
        __syncthreads();
    }
    #pragma unroll
    for (int i = 0; i < 4; i++)
        #pragma unroll
        for (int j = 0; j < 4; j++)
            g_Z0[(size_t)(bm + ty * 4 + i) * CLS + tx * 4 + j] =
                acc[i][j] + g_bias[tx * 4 + j];
}

// ---------------- kernel 3: propagation, tf32 mma + per-tile fp32 re-accumulate ----------------
#define BM 128
#define BN 64
#define BK 32
#define KT (N_ROWS / BK)      // 512
#define STAGES 3
#define A_STRIDE 36           // (r*36+k)%32 = (r*4+k)%32 -> conflict-free
#define B_STRIDE 72           // (k*72+c)%32 = (k*8+c)%32 -> conflict-free
#define ASZ (BM * A_STRIDE)
#define BSZ (BK * B_STRIDE)
#define SMEM_BYTES ((STAGES * (ASZ + BSZ)) * 4)  // 82944

__device__ __forceinline__ void cp_async16(void* smem, const void* gmem) {
    uint32_t s = (uint32_t)__cvta_generic_to_shared(smem);
    asm volatile("cp.async.cg.shared.global [%0], [%1], 16;\n" :: "r"(s), "l"(gmem));
}
__device__ __forceinline__ uint32_t f2tf32(float f) {
    uint32_t u;
    asm volatile("cvt.rna.tf32.f32 %0, %1;\n" : "=r"(u) : "f"(f));
    return u;
}
__device__ __forceinline__ void mma_tf32(float c[4],
                                         uint32_t a0, uint32_t a1, uint32_t a2, uint32_t a3,
                                         uint32_t b0, uint32_t b1) {
    asm volatile(
        "mma.sync.aligned.m16n8k8.row.col.f32.tf32.tf32.f32 "
        "{%0,%1,%2,%3}, {%4,%5,%6,%7}, {%8,%9}, {%0,%1,%2,%3};\n"
        : "+f"(c[0]), "+f"(c[1]), "+f"(c[2]), "+f"(c[3])
        : "r"(a0), "r"(a1), "r"(a2), "r"(a3), "r"(b0), "r"(b1));
}

__global__ __launch_bounds__(256, 1)
void prop_kernel(const float* __restrict__ adj, int it) {
    const float* Zin  = (it == 0) ? g_Z0 : ((it & 1) ? g_ZA : g_ZB);
    float*       Zout = (it & 1) ? g_ZB : g_ZA;

    extern __shared__ float smem[];
    float* Abase = smem;                 // [STAGES][BM][A_STRIDE]
    float* Bbase = smem + STAGES * ASZ;  // [STAGES][BK][B_STRIDE]

    const int tid   = threadIdx.x;
    const int lane  = tid & 31;
    const int warp  = tid >> 5;
    const int warpM = warp >> 1;   // 0..3 -> 32-row slice
    const int warpN = warp & 1;    // 0..1 -> 32-col slice
    const int bm    = blockIdx.x * BM;

    auto load_tiles = [&](int s, int k0) {
        float* As = Abase + s * ASZ;
        float* Bs = Bbase + s * BSZ;
        #pragma unroll
        for (int j = 0; j < 4; j++) {               // A: 128x32 floats = 1024 float4
            int i = tid + j * 256;
            int r = i >> 3, c4 = i & 7;
            cp_async16(&As[r * A_STRIDE + c4 * 4],
                       adj + (size_t)(bm + r) * N_ROWS + k0 + c4 * 4);
        }
        #pragma unroll
        for (int j = 0; j < 2; j++) {               // B: 32x64 floats = 512 float4
            int i = tid + j * 256;
            int r = i >> 4, c4 = i & 15;
            cp_async16(&Bs[r * B_STRIDE + c4 * 4],
                       Zin + (size_t)(k0 + r) * CLS + c4 * 4);
        }
        asm volatile("cp.async.commit_group;\n");
    };

    float acc[2][4][4];     // persistent fp32 accumulator (exact FADD chain)
    #pragma unroll
    for (int mt = 0; mt < 2; mt++)
        #pragma unroll
        for (int nt = 0; nt < 4; nt++)
            #pragma unroll
            for (int i = 0; i < 4; i++) acc[mt][nt][i] = 0.f;

    load_tiles(0, 0);
    load_tiles(1, BK);

    for (int kt = 0; kt < KT; kt++) {
        asm volatile("cp.async.wait_group 1;\n");
        __syncthreads();

        int nk = kt + 2;
        if (nk < KT) load_tiles(nk % STAGES, nk * BK);
        else         asm volatile("cp.async.commit_group;\n");

        const float* As = Abase + (kt % STAGES) * ASZ;
        const float* Bs = Bbase + (kt % STAGES) * BSZ;

        // short-chain mma accumulator, reset each k-tile (32 real k = 4 chained mmas)
        float ctile[2][4][4];
        #pragma unroll
        for (int mt = 0; mt < 2; mt++)
            #pragma unroll
            for (int nt = 0; nt < 4; nt++)
                #pragma unroll
                for (int i = 0; i < 4; i++) ctile[mt][nt][i] = 0.f;

        #pragma unroll
        for (int kk = 0; kk < 4; kk++) {
            int k = kk * 8 + (lane & 3);
            uint32_t a[2][4];
            #pragma unroll
            for (int mt = 0; mt < 2; mt++) {
                int r = warpM * 32 + mt * 16 + (lane >> 2);
                a[mt][0] = f2tf32(As[r * A_STRIDE + k]);
                a[mt][1] = f2tf32(As[(r + 8) * A_STRIDE + k]);
                a[mt][2] = f2tf32(As[r * A_STRIDE + k + 4]);
                a[mt][3] = f2tf32(As[(r + 8) * A_STRIDE + k + 4]);
            }
            #pragma unroll
            for (int nt = 0; nt < 4; nt++) {
                int c = warpN * 32 + nt * 8 + (lane >> 2);
                uint32_t b0 = f2tf32(Bs[k * B_STRIDE + c]);
                uint32_t b1 = f2tf32(Bs[(k + 4) * B_STRIDE + c]);
                #pragma unroll
                for (int mt = 0; mt < 2; mt++)
                    mma_tf32(ctile[mt][nt], a[mt][0], a[mt][1], a[mt][2], a[mt][3], b0, b1);
            }
        }

        // exact fp32 add of the tile partial into the persistent accumulator
        #pragma unroll
        for (int mt = 0; mt < 2; mt++)
            #pragma unroll
            for (int nt = 0; nt < 4; nt++)
                #pragma unroll
                for (int i = 0; i < 4; i++) acc[mt][nt][i] += ctile[mt][nt][i];
    }

    // epilogue: Zout = 0.9*acc + 0.1*Z0
    #pragma unroll
    for (int mt = 0; mt < 2; mt++) {
        #pragma unroll
        for (int nt = 0; nt < 4; nt++) {
            int r0 = bm + warpM * 32 + mt * 16 + (lane >> 2);
            int c0 = warpN * 32 + nt * 8 + (lane & 3) * 2;
            #pragma unroll
            for (int i = 0; i < 4; i++) {
                int r = r0 + ((i >= 2) ? 8 : 0);
                int c = c0 + (i & 1);
                size_t idx = (size_t)r * CLS + c;
                Zout[idx] = 0.9f * acc[mt][nt][i] + 0.1f * g_Z0[idx];
            }
        }
    }
}

// ---------------- kernel 4: row-wise log_softmax (warp per row) ----------------
__global__ __launch_bounds__(256)
void lsm_kernel(float* __restrict__ out) {
    int row  = blockIdx.x * 8 + (threadIdx.x >> 5);
    int lane = threadIdx.x & 31;
    const float* zr = g_ZB + (size_t)row * CLS;   // iteration 9 (odd) lands in g_ZB
    float v0 = zr[lane], v1 = zr[lane + 32];
    float m = fmaxf(v0, v1);
    #pragma unroll
    for (int o = 16; o > 0; o >>= 1) m = fmaxf(m, __shfl_xor_sync(0xffffffffu, m, o));
    float e = expf(v0 - m) + expf(v1 - m);
    #pragma unroll
    for (int o = 16; o > 0; o >>= 1) e += __shfl_xor_sync(0xffffffffu, e, o);
    float l = m + logf(e);
    out[(size_t)row * CLS + lane]      = v0 - l;
    out[(size_t)row * CLS + lane + 32] = v1 - l;
}

// ---------------- launch ----------------
extern "C" void kernel_launch(void* const* d_in, const int* in_sizes, int n_in,
                              void* d_out, int out_size) {
    const float *h = nullptr, *adj = nullptr, *W1 = nullptr,
                *b1 = nullptr, *W2 = nullptr, *b2 = nullptr;
    for (int i = 0; i < n_in; i++) {
        switch (in_sizes[i]) {
            case N_ROWS * FEATS:  h   = (const float*)d_in[i]; break;
            case 268435456:       adj = (const float*)d_in[i]; break;
            case FEATS * HID:     W1  = (const float*)d_in[i]; break;
            case HID:             b1  = (const float*)d_in[i]; break;
            case HID * CLS:       W2  = (const float*)d_in[i]; break;
            case CLS:             b2  = (const float*)d_in[i]; break;
            default: break;
        }
    }

    cudaFuncSetAttribute(prop_kernel, cudaFuncAttributeMaxDynamicSharedMemorySize,
                         SMEM_BYTES);

    fuse_w_kernel<<<(FEATS * CLS + CLS + 255) / 256, 256>>>(W1, b1, W2, b2);
    z0_kernel<<<N_ROWS / Z0_BM, 256>>>(h);
    for (int it = 0; it < NITER; it++)
        prop_kernel<<<N_ROWS / BM, 256, SMEM_BYTES>>>(adj, it);
    lsm_kernel<<<N_ROWS / 8, 256>>>((float*)d_out);
}